// round 6
// baseline (speedup 1.0000x reference)
#include <cuda_runtime.h>
#include <cstdint>

// CodedNet: z[b,i,j] = sum_ch x[b,i,j,ch] * bk[(i-ch)%256, j, ch]
// x: [32,256,256,28] f32   bk: [256,256,28] f32 (binary {0,1})   out: [32,256,256] f32
//
// R6: (1) PDL overlap: pack triggers early; main issues its TMA prologue, then
//     grid-dep-syncs only before consuming the packed mask.
//     (2) per-warp private 3-stage TMA pipelines (no __syncthreads in main loop),
//     43KB smem/CTA -> 4 CTAs/SM.

#define PDIM   256
#define CHN    28
#define JT     128
#define NBPER  16                     // batches per block (grid = 256*2*2 = 1024)
#define STAGES 3                      // stages per WARP
#define WSLAB  3584                   // bytes per warp slab (32 px * 28 ch * 4B)
#define NWARP  4
#define SMEM_MAIN (NWARP * STAGES * WSLAB + NWARP * STAGES * 8)

__device__ uint32_t g_V[PDIM * PDIM];   // bit ch = (bk[r][j][ch] != 0)

// ---- K0: pack mask bits along channel; one thread per pixel ----
__global__ __launch_bounds__(128)
void pack_kernel(const float* __restrict__ bk)
{
    const int p = blockIdx.x * 128 + threadIdx.x;
    const float4* src = reinterpret_cast<const float4*>(bk) + p * 7;
    float4 v[7];
#pragma unroll
    for (int k = 0; k < 7; k++) v[k] = src[k];
    uint32_t w = 0;
#pragma unroll
    for (int k = 0; k < 7; k++) {
        if (v[k].x != 0.f) w |= 1u << (4 * k + 0);
        if (v[k].y != 0.f) w |= 1u << (4 * k + 1);
        if (v[k].z != 0.f) w |= 1u << (4 * k + 2);
        if (v[k].w != 0.f) w |= 1u << (4 * k + 3);
    }
    g_V[p] = w;
    cudaTriggerProgrammaticLaunchCompletion();   // writes above are visible to dep grid
}

// ---- mbarrier / bulk-copy helpers ----
__device__ __forceinline__ uint32_t smem_u32(const void* p) {
    return (uint32_t)__cvta_generic_to_shared(p);
}
__device__ __forceinline__ void mbar_init(uint32_t mb, uint32_t cnt) {
    asm volatile("mbarrier.init.shared.b64 [%0], %1;" :: "r"(mb), "r"(cnt) : "memory");
}
__device__ __forceinline__ void mbar_expect_tx(uint32_t mb, uint32_t bytes) {
    asm volatile("mbarrier.arrive.expect_tx.shared.b64 _, [%0], %1;" :: "r"(mb), "r"(bytes) : "memory");
}
__device__ __forceinline__ void bulk_g2s(uint32_t dst, const void* src, uint32_t bytes, uint32_t mb) {
    asm volatile("cp.async.bulk.shared::cluster.global.mbarrier::complete_tx::bytes [%0], [%1], %2, [%3];"
                 :: "r"(dst), "l"(src), "r"(bytes), "r"(mb) : "memory");
}
__device__ __forceinline__ void mbar_wait_parity(uint32_t mb, uint32_t parity) {
    uint32_t done;
    asm volatile(
        "{\n\t.reg .pred p;\n\t"
        "mbarrier.try_wait.parity.acquire.cta.shared::cta.b64 p, [%1], %2;\n\t"
        "selp.b32 %0, 1, 0, p;\n\t}"
        : "=r"(done) : "r"(mb), "r"(parity) : "memory");
    if (!done) {
        asm volatile(
            "{\n\t.reg .pred P1;\n\t"
            "WL_%=:\n\t"
            "mbarrier.try_wait.parity.acquire.cta.shared::cta.b64 P1, [%0], %1, 0x989680;\n\t"
            "@P1 bra.uni WD_%=;\n\t"
            "bra.uni WL_%=;\n\t"
            "WD_%=:\n\t}"
            :: "r"(mb), "r"(parity) : "memory");
    }
}

// ---- main streaming kernel: per-warp private pipelines ----
__global__ __launch_bounds__(128)
void codednet_kernel(const float* __restrict__ x, float* __restrict__ out)
{
    extern __shared__ __align__(16) char smem[];
    const int tid  = threadIdx.x;
    const int wrp  = tid >> 5;
    const int lane = tid & 31;
    const int bx   = blockIdx.x;                 // 0..1023
    const int i    = bx >> 2;
    const int j0   = ((bx >> 1) & 1) * JT;
    const int b0   = (bx & 1) * NBPER;
    const int j    = j0 + wrp * 32 + lane;       // this thread's pixel column

    // warp-private slab + mbarrier bases
    char* wslab = smem + (size_t)wrp * STAGES * WSLAB;
    const uint32_t mbb = smem_u32(smem) + NWARP * STAGES * WSLAB + wrp * STAGES * 8;

    // gmem base for this warp's 32-pixel strip
    const char* gx = reinterpret_cast<const char*>(x);
    const size_t strip0 = ((size_t)i * PDIM + j0 + wrp * 32) * CHN * 4;   // bytes
    const size_t bstr   = (size_t)PDIM * PDIM * CHN * 4;                  // bytes/batch

    if (lane == 0) {
#pragma unroll
        for (int s = 0; s < STAGES; s++) mbar_init(mbb + 8 * s, 1);
        asm volatile("fence.proxy.async.shared::cta;" ::: "memory");
    }
    __syncwarp();

    // prologue: fill this warp's pipeline (independent of the mask)
    if (lane == 0) {
#pragma unroll
        for (int s = 0; s < STAGES; s++) {
            mbar_expect_tx(mbb + 8 * s, WSLAB);
            bulk_g2s(smem_u32(wslab) + s * WSLAB,
                     gx + strip0 + (size_t)(b0 + s) * bstr, WSLAB, mbb + 8 * s);
        }
    }

    // PDL: wait for pack_kernel before consuming g_V
    cudaGridDependencySynchronize();

    float4 mv[7];
#pragma unroll
    for (int k = 0; k < 7; k++) {
        int c0 = 4 * k;
        uint32_t v0 = g_V[(((i - (c0 + 0)) & (PDIM - 1)) << 8) + j];
        uint32_t v1 = g_V[(((i - (c0 + 1)) & (PDIM - 1)) << 8) + j];
        uint32_t v2 = g_V[(((i - (c0 + 2)) & (PDIM - 1)) << 8) + j];
        uint32_t v3 = g_V[(((i - (c0 + 3)) & (PDIM - 1)) << 8) + j];
        mv[k].x = (v0 >> (c0 + 0)) & 1u ? 1.f : 0.f;
        mv[k].y = (v1 >> (c0 + 1)) & 1u ? 1.f : 0.f;
        mv[k].z = (v2 >> (c0 + 2)) & 1u ? 1.f : 0.f;
        mv[k].w = (v3 >> (c0 + 3)) & 1u ? 1.f : 0.f;
    }

#pragma unroll 1
    for (int b = 0; b < NBPER; b++) {
        const int s = b % STAGES;
        const uint32_t parity = (uint32_t)(b / STAGES) & 1u;
        mbar_wait_parity(mbb + 8 * s, parity);

        const float4* p = reinterpret_cast<const float4*>(wslab + s * WSLAB) + lane * 7;
        float a0 = 0.f, a1 = 0.f, a2 = 0.f, a3 = 0.f;
#pragma unroll
        for (int k = 0; k < 7; k++) {
            float4 v = p[k];
            a0 += v.x * mv[k].x;  a1 += v.y * mv[k].y;
            a2 += v.z * mv[k].z;  a3 += v.w * mv[k].w;
        }
        out[((size_t)(b0 + b) * PDIM + i) * PDIM + j] = (a0 + a1) + (a2 + a3);

        // all lanes' LDS results are consumed (registers) before this point
        __syncwarp();
        if (lane == 0 && b + STAGES < NBPER) {
            mbar_expect_tx(mbb + 8 * s, WSLAB);
            bulk_g2s(smem_u32(wslab) + s * WSLAB,
                     gx + strip0 + (size_t)(b0 + b + STAGES) * bstr, WSLAB, mbb + 8 * s);
        }
    }
}

extern "C" void kernel_launch(void* const* d_in, const int* in_sizes, int n_in,
                              void* d_out, int out_size)
{
    const float* x  = (const float*)d_in[0];
    const float* bk = (const float*)d_in[1];
    float* out = (float*)d_out;
    (void)in_sizes; (void)n_in; (void)out_size;

    cudaFuncSetAttribute(codednet_kernel,
                         cudaFuncAttributeMaxDynamicSharedMemorySize, SMEM_MAIN);

    pack_kernel<<<PDIM * PDIM / 128, 128>>>(bk);

    cudaLaunchConfig_t cfg = {};
    cfg.gridDim  = dim3(PDIM * 2 * 2, 1, 1);
    cfg.blockDim = dim3(128, 1, 1);
    cfg.dynamicSmemBytes = SMEM_MAIN;
    cudaLaunchAttribute attrs[1];
    attrs[0].id = cudaLaunchAttributeProgrammaticStreamSerialization;
    attrs[0].val.programmaticStreamSerializationAllowed = 1;
    cfg.attrs = attrs;
    cfg.numAttrs = 1;
    cudaLaunchKernelEx(&cfg, codednet_kernel, x, out);
}

// round 7
// speedup vs baseline: 1.2459x; 1.2459x over previous
#include <cuda_runtime.h>
#include <cstdint>

// CodedNet: z[b,i,j] = sum_ch x[b,i,j,ch] * bk[(i-ch)%256, j, ch]
// x: [32,256,256,28] f32   bk: [256,256,28] f32 (binary {0,1})   out: [32,256,256] f32
//
// R7: single-wave persistent schedule. Work = 16384 slabs (slab = one batch x one
// 128-pixel half-row, 14336 B). grid = 456 (152 SM x 3 CTAs, smem 71.7KB each);
// each CTA processes a contiguous chunk (35-36 slabs, batch-fastest so the mask
// word changes <=2x per CTA). Engine = R5's 5-stage CTA-wide cp.async.bulk
// pipeline (the configuration measured at DRAM-saturation-while-busy).
// PDL hides the mask-pack pre-pass under the main kernel's pipeline fill.

#define PDIM   256
#define CHN    28
#define JT     128
#define STAGES 5
#define SLAB_F4    896                 // float4 per slab
#define SLAB_BYTES 14336
#define SMEM_MAIN  (STAGES * SLAB_BYTES + STAGES * 8)
#define NSLABS 16384                   // 32 batches * 256 rows * 2 halves
#define NCTAS  456                     // 152 SMs * 3 CTAs -> exactly one wave

__device__ uint32_t g_V[PDIM * PDIM];  // bit ch = (bk[r][j][ch] != 0)

// ---- K0: pack mask bits along channel; one thread per pixel ----
__global__ __launch_bounds__(128)
void pack_kernel(const float* __restrict__ bk)
{
    const int p = blockIdx.x * 128 + threadIdx.x;
    const float4* src = reinterpret_cast<const float4*>(bk) + p * 7;
    float4 v[7];
#pragma unroll
    for (int k = 0; k < 7; k++) v[k] = src[k];
    uint32_t w = 0;
#pragma unroll
    for (int k = 0; k < 7; k++) {
        if (v[k].x != 0.f) w |= 1u << (4 * k + 0);
        if (v[k].y != 0.f) w |= 1u << (4 * k + 1);
        if (v[k].z != 0.f) w |= 1u << (4 * k + 2);
        if (v[k].w != 0.f) w |= 1u << (4 * k + 3);
    }
    g_V[p] = w;
    cudaTriggerProgrammaticLaunchCompletion();
}

// ---- mbarrier / bulk-copy helpers ----
__device__ __forceinline__ uint32_t smem_u32(const void* p) {
    return (uint32_t)__cvta_generic_to_shared(p);
}
__device__ __forceinline__ void mbar_init(uint32_t mb, uint32_t cnt) {
    asm volatile("mbarrier.init.shared.b64 [%0], %1;" :: "r"(mb), "r"(cnt) : "memory");
}
__device__ __forceinline__ void mbar_expect_tx(uint32_t mb, uint32_t bytes) {
    asm volatile("mbarrier.arrive.expect_tx.shared.b64 _, [%0], %1;" :: "r"(mb), "r"(bytes) : "memory");
}
__device__ __forceinline__ void bulk_g2s(uint32_t dst, const void* src, uint32_t bytes, uint32_t mb) {
    asm volatile("cp.async.bulk.shared::cluster.global.mbarrier::complete_tx::bytes [%0], [%1], %2, [%3];"
                 :: "r"(dst), "l"(src), "r"(bytes), "r"(mb) : "memory");
}
__device__ __forceinline__ void mbar_wait_parity(uint32_t mb, uint32_t parity) {
    uint32_t done;
    asm volatile(
        "{\n\t.reg .pred p;\n\t"
        "mbarrier.try_wait.parity.acquire.cta.shared::cta.b64 p, [%1], %2;\n\t"
        "selp.b32 %0, 1, 0, p;\n\t}"
        : "=r"(done) : "r"(mb), "r"(parity) : "memory");
    if (!done) {
        asm volatile(
            "{\n\t.reg .pred P1;\n\t"
            "WL_%=:\n\t"
            "mbarrier.try_wait.parity.acquire.cta.shared::cta.b64 P1, [%0], %1, 0x989680;\n\t"
            "@P1 bra.uni WD_%=;\n\t"
            "bra.uni WL_%=;\n\t"
            "WD_%=:\n\t}"
            :: "r"(mb), "r"(parity) : "memory");
    }
}

// slab s -> coords: b = s & 31 (fastest), q = s >> 5, i = q >> 1, half = q & 1.
__device__ __forceinline__ size_t slab_gmem_off(int s) {
    int b = s & 31, q = s >> 5;
    // ((b*65536) + q*128) pixels * 112 bytes
    return ((size_t)b * (PDIM * PDIM) + (size_t)q * JT) * (CHN * 4);
}

// ---- main persistent streaming kernel ----
__global__ __launch_bounds__(128)
void codednet_kernel(const float* __restrict__ x, float* __restrict__ out)
{
    extern __shared__ __align__(16) char smem[];
    float4* xs = reinterpret_cast<float4*>(smem);
    const uint32_t mb0 = smem_u32(smem) + STAGES * SLAB_BYTES;

    const int tid = threadIdx.x;
    const int c   = blockIdx.x;
    const int s_beg = (int)(((long long)c * NSLABS) / NCTAS);
    const int s_end = (int)(((long long)(c + 1) * NSLABS) / NCTAS);
    const int cnt   = s_end - s_beg;

    if (tid == 0) {
#pragma unroll
        for (int s = 0; s < STAGES; s++) mbar_init(mb0 + 8 * s, 1);
        asm volatile("fence.proxy.async.shared::cta;" ::: "memory");
    }
    __syncthreads();

    // prologue: fill the pipeline (mask-independent -> overlaps pack via PDL)
    const char* gx = reinterpret_cast<const char*>(x);
    if (tid == 0) {
#pragma unroll
        for (int st = 0; st < STAGES; st++) {
            if (st < cnt) {
                mbar_expect_tx(mb0 + 8 * st, SLAB_BYTES);
                bulk_g2s(smem_u32(smem) + st * SLAB_BYTES,
                         gx + slab_gmem_off(s_beg + st), SLAB_BYTES, mb0 + 8 * st);
            }
        }
    }

    // PDL: mask becomes readable only now
    cudaGridDependencySynchronize();

    int q_prev = -1;
    float4 mv[7];
    int i = 0, j = 0;

#pragma unroll 1
    for (int it = 0; it < cnt; it++) {
        const int s   = s_beg + it;
        const int stg = it % STAGES;
        const uint32_t parity = (uint32_t)(it / STAGES) & 1u;
        mbar_wait_parity(mb0 + 8 * stg, parity);

        const int q = s >> 5;
        if (q != q_prev) {                 // <=2-3 times per CTA
            q_prev = q;
            i = q >> 1;
            j = (q & 1) * JT + tid;
#pragma unroll
            for (int k = 0; k < 7; k++) {
                int c0 = 4 * k;
                uint32_t v0 = g_V[(((i - (c0 + 0)) & (PDIM - 1)) << 8) + j];
                uint32_t v1 = g_V[(((i - (c0 + 1)) & (PDIM - 1)) << 8) + j];
                uint32_t v2 = g_V[(((i - (c0 + 2)) & (PDIM - 1)) << 8) + j];
                uint32_t v3 = g_V[(((i - (c0 + 3)) & (PDIM - 1)) << 8) + j];
                mv[k].x = (v0 >> (c0 + 0)) & 1u ? 1.f : 0.f;
                mv[k].y = (v1 >> (c0 + 1)) & 1u ? 1.f : 0.f;
                mv[k].z = (v2 >> (c0 + 2)) & 1u ? 1.f : 0.f;
                mv[k].w = (v3 >> (c0 + 3)) & 1u ? 1.f : 0.f;
            }
        }

        const float4* p = xs + stg * SLAB_F4 + tid * 7;    // 112B stride: conflict-free
        float a0 = 0.f, a1 = 0.f, a2 = 0.f, a3 = 0.f;
#pragma unroll
        for (int k = 0; k < 7; k++) {
            float4 v = p[k];
            a0 += v.x * mv[k].x;  a1 += v.y * mv[k].y;
            a2 += v.z * mv[k].z;  a3 += v.w * mv[k].w;
        }
        const int b = s & 31;
        out[((size_t)b * PDIM + i) * PDIM + j] = (a0 + a1) + (a2 + a3);

        __syncthreads();   // all threads done reading stage stg -> safe to refill
        if (tid == 0 && it + STAGES < cnt) {
            mbar_expect_tx(mb0 + 8 * stg, SLAB_BYTES);
            bulk_g2s(smem_u32(smem) + stg * SLAB_BYTES,
                     gx + slab_gmem_off(s + STAGES), SLAB_BYTES, mb0 + 8 * stg);
        }
    }
}

extern "C" void kernel_launch(void* const* d_in, const int* in_sizes, int n_in,
                              void* d_out, int out_size)
{
    const float* x  = (const float*)d_in[0];
    const float* bk = (const float*)d_in[1];
    float* out = (float*)d_out;
    (void)in_sizes; (void)n_in; (void)out_size;

    cudaFuncSetAttribute(codednet_kernel,
                         cudaFuncAttributeMaxDynamicSharedMemorySize, SMEM_MAIN);

    pack_kernel<<<PDIM * PDIM / 128, 128>>>(bk);

    cudaLaunchConfig_t cfg = {};
    cfg.gridDim  = dim3(NCTAS, 1, 1);
    cfg.blockDim = dim3(128, 1, 1);
    cfg.dynamicSmemBytes = SMEM_MAIN;
    cudaLaunchAttribute attrs[1];
    attrs[0].id = cudaLaunchAttributeProgrammaticStreamSerialization;
    attrs[0].val.programmaticStreamSerializationAllowed = 1;
    cfg.attrs = attrs;
    cfg.numAttrs = 1;
    cudaLaunchKernelEx(&cfg, codednet_kernel, x, out);
}

// round 8
// speedup vs baseline: 1.2899x; 1.0353x over previous
#include <cuda_runtime.h>
#include <cstdint>

// CodedNet: z[b,i,j] = sum_ch x[b,i,j,ch] * bk[(i-ch)%256, j, ch]
// x: [32,256,256,28] f32   bk: [256,256,28] f32 (binary {0,1})   out: [32,256,256] f32
//
// R8: R5's measured-at-LTS-cap engine (grid 1024, 5-stage CTA-wide 14336B
// cp.async.bulk pipeline, 6278 GB/s ~= chip LTS ceiling) + PDL: the mask-pack
// pre-pass overlaps the main kernel's TMA prologue; grid-dep-sync only guards
// the g_V decode. Target: recover the ~6us pack/launch overhead.

#define PDIM   256
#define CHN    28
#define JT     128
#define NBPER  16                 // batches per block (grid = 256*2*2 = 1024)
#define STAGES 5
#define SLAB_F4    896
#define SLAB_BYTES 14336
#define SMEM_MAIN  (STAGES * SLAB_BYTES + STAGES * 8)

__device__ uint32_t g_V[PDIM * PDIM];   // bit ch = (bk[r][j][ch] != 0)

// ---- K0: pack mask bits along channel; one thread per pixel ----
__global__ __launch_bounds__(128)
void pack_kernel(const float* __restrict__ bk)
{
    const int p = blockIdx.x * 128 + threadIdx.x;
    const float4* src = reinterpret_cast<const float4*>(bk) + p * 7;
    float4 v[7];
#pragma unroll
    for (int k = 0; k < 7; k++) v[k] = src[k];          // MLP=7
    uint32_t w = 0;
#pragma unroll
    for (int k = 0; k < 7; k++) {
        if (v[k].x != 0.f) w |= 1u << (4 * k + 0);
        if (v[k].y != 0.f) w |= 1u << (4 * k + 1);
        if (v[k].z != 0.f) w |= 1u << (4 * k + 2);
        if (v[k].w != 0.f) w |= 1u << (4 * k + 3);
    }
    g_V[p] = w;
    cudaTriggerProgrammaticLaunchCompletion();
}

// ---- mbarrier / bulk-copy helpers ----
__device__ __forceinline__ uint32_t smem_u32(const void* p) {
    return (uint32_t)__cvta_generic_to_shared(p);
}
__device__ __forceinline__ void mbar_init(uint32_t mb, uint32_t cnt) {
    asm volatile("mbarrier.init.shared.b64 [%0], %1;" :: "r"(mb), "r"(cnt) : "memory");
}
__device__ __forceinline__ void mbar_expect_tx(uint32_t mb, uint32_t bytes) {
    asm volatile("mbarrier.arrive.expect_tx.shared.b64 _, [%0], %1;" :: "r"(mb), "r"(bytes) : "memory");
}
__device__ __forceinline__ void bulk_g2s(uint32_t dst, const void* src, uint32_t bytes, uint32_t mb) {
    asm volatile("cp.async.bulk.shared::cluster.global.mbarrier::complete_tx::bytes [%0], [%1], %2, [%3];"
                 :: "r"(dst), "l"(src), "r"(bytes), "r"(mb) : "memory");
}
__device__ __forceinline__ void mbar_wait_parity(uint32_t mb, uint32_t parity) {
    uint32_t done;
    asm volatile(
        "{\n\t.reg .pred p;\n\t"
        "mbarrier.try_wait.parity.acquire.cta.shared::cta.b64 p, [%1], %2;\n\t"
        "selp.b32 %0, 1, 0, p;\n\t}"
        : "=r"(done) : "r"(mb), "r"(parity) : "memory");
    if (!done) {
        asm volatile(
            "{\n\t.reg .pred P1;\n\t"
            "WL_%=:\n\t"
            "mbarrier.try_wait.parity.acquire.cta.shared::cta.b64 P1, [%0], %1, 0x989680;\n\t"
            "@P1 bra.uni WD_%=;\n\t"
            "bra.uni WL_%=;\n\t"
            "WD_%=:\n\t}"
            :: "r"(mb), "r"(parity) : "memory");
    }
}

// ---- main streaming kernel (R5 engine) ----
__global__ __launch_bounds__(128)
void codednet_kernel(const float* __restrict__ x, float* __restrict__ out)
{
    extern __shared__ __align__(16) char smem[];
    float4* xs = reinterpret_cast<float4*>(smem);
    const uint32_t mb0 = smem_u32(smem) + STAGES * SLAB_BYTES;

    const int tid = threadIdx.x;
    const int bx  = blockIdx.x;                 // 0..1023
    const int i   = bx >> 2;
    const int j0  = ((bx >> 1) & 1) * JT;
    const int b0  = (bx & 1) * NBPER;
    const int j   = j0 + tid;

    if (tid == 0) {
#pragma unroll
        for (int s = 0; s < STAGES; s++) mbar_init(mb0 + 8 * s, 1);
        asm volatile("fence.proxy.async.shared::cta;" ::: "memory");
    }
    __syncthreads();

    // prologue: fill the pipeline (mask-independent -> overlaps pack via PDL)
    const char* gx = reinterpret_cast<const char*>(x);
    const size_t slab0 = ((size_t)i * PDIM + j0) * CHN * 4;
    const size_t bstr  = (size_t)PDIM * PDIM * CHN * 4;
    if (tid == 0) {
#pragma unroll
        for (int s = 0; s < STAGES; s++) {
            mbar_expect_tx(mb0 + 8 * s, SLAB_BYTES);
            bulk_g2s(smem_u32(smem) + s * SLAB_BYTES,
                     gx + slab0 + (size_t)(b0 + s) * bstr, SLAB_BYTES, mb0 + 8 * s);
        }
    }

    // PDL: pack results readable only after this
    cudaGridDependencySynchronize();

    // 28 coalesced uint32 loads, L2-resident (g_V = 256 KB)
    float4 mv[7];
#pragma unroll
    for (int k = 0; k < 7; k++) {
        int c0 = 4 * k;
        uint32_t v0 = g_V[(((i - (c0 + 0)) & (PDIM - 1)) << 8) + j];
        uint32_t v1 = g_V[(((i - (c0 + 1)) & (PDIM - 1)) << 8) + j];
        uint32_t v2 = g_V[(((i - (c0 + 2)) & (PDIM - 1)) << 8) + j];
        uint32_t v3 = g_V[(((i - (c0 + 3)) & (PDIM - 1)) << 8) + j];
        mv[k].x = (v0 >> (c0 + 0)) & 1u ? 1.f : 0.f;
        mv[k].y = (v1 >> (c0 + 1)) & 1u ? 1.f : 0.f;
        mv[k].z = (v2 >> (c0 + 2)) & 1u ? 1.f : 0.f;
        mv[k].w = (v3 >> (c0 + 3)) & 1u ? 1.f : 0.f;
    }

#pragma unroll 1
    for (int b = 0; b < NBPER; b++) {
        const int s = b % STAGES;
        const uint32_t parity = (uint32_t)(b / STAGES) & 1u;
        mbar_wait_parity(mb0 + 8 * s, parity);

        const float4* p = xs + s * SLAB_F4 + tid * 7;   // 112B stride: conflict-free
        float a0 = 0.f, a1 = 0.f, a2 = 0.f, a3 = 0.f;
#pragma unroll
        for (int k = 0; k < 7; k++) {
            float4 v = p[k];
            a0 += v.x * mv[k].x;  a1 += v.y * mv[k].y;
            a2 += v.z * mv[k].z;  a3 += v.w * mv[k].w;
        }
        out[((size_t)(b0 + b) * PDIM + i) * PDIM + j] = (a0 + a1) + (a2 + a3);

        __syncthreads();   // all threads done reading stage s -> safe to refill
        if (tid == 0 && b + STAGES < NBPER) {
            mbar_expect_tx(mb0 + 8 * s, SLAB_BYTES);
            bulk_g2s(smem_u32(smem) + s * SLAB_BYTES,
                     gx + slab0 + (size_t)(b0 + b + STAGES) * bstr, SLAB_BYTES, mb0 + 8 * s);
        }
    }
}

extern "C" void kernel_launch(void* const* d_in, const int* in_sizes, int n_in,
                              void* d_out, int out_size)
{
    const float* x  = (const float*)d_in[0];
    const float* bk = (const float*)d_in[1];
    float* out = (float*)d_out;
    (void)in_sizes; (void)n_in; (void)out_size;

    cudaFuncSetAttribute(codednet_kernel,
                         cudaFuncAttributeMaxDynamicSharedMemorySize, SMEM_MAIN);

    pack_kernel<<<PDIM * PDIM / 128, 128>>>(bk);

    cudaLaunchConfig_t cfg = {};
    cfg.gridDim  = dim3(PDIM * 2 * 2, 1, 1);
    cfg.blockDim = dim3(128, 1, 1);
    cfg.dynamicSmemBytes = SMEM_MAIN;
    cudaLaunchAttribute attrs[1];
    attrs[0].id = cudaLaunchAttributeProgrammaticStreamSerialization;
    attrs[0].val.programmaticStreamSerializationAllowed = 1;
    cfg.attrs = attrs;
    cfg.numAttrs = 1;
    cudaLaunchKernelEx(&cfg, codednet_kernel, x, out);
}